// round 4
// baseline (speedup 1.0000x reference)
#include <cuda_runtime.h>
#include <cuda_bf16.h>

// Problem constants (past_grid [32, 64, 192, 192] fp32)
#define C_  32
#define D_  64
#define H_  192
#define W_  192
#define HW_  (H_ * W_)            // 36864
#define DHW_ (D_ * HW_)           // 2359296

#define SSTRIDE 328               // smem floats per channel

// Fused affine coefficients
__device__ float g_coef[12];

__global__ void setup_kernel(const float* __restrict__ voxp,
                             const float* __restrict__ Rp,
                             const float* __restrict__ tp,
                             const float* __restrict__ Rc,
                             const float* __restrict__ tc) {
    if (threadIdx.x != 0 || blockIdx.x != 0) return;
    double vox = (double)voxp[0];
    double M[3][3], b[3];
    for (int j = 0; j < 3; j++) {
        for (int k = 0; k < 3; k++) {
            double s = 0.0;
            for (int i = 0; i < 3; i++) s += (double)Rp[i*3+j] * (double)Rc[i*3+k];
            M[j][k] = s;
        }
        double sb = 0.0;
        for (int i = 0; i < 3; i++) sb += (double)Rp[i*3+j] * ((double)tc[i] - (double)tp[i]);
        b[j] = sb;
    }
    const double ch = (H_ - 1) * 0.5, cw = (W_ - 1) * 0.5, cd = (D_ - 1) * 0.5;
    const int    qi[3] = {2, 0, 1};
    const double A[3]  = { (double)W_ / (vox * (D_ - 1)),
                           (double)H_ / (vox * (H_ - 1)),
                           (double)D_ / (vox * (W_ - 1)) };
    const double Cadd[3] = { (W_ - 1) * 0.5, (H_ - 1) * 0.5, (D_ - 1) * 0.5 };
    for (int r = 0; r < 3; r++) {
        int j = qi[r];
        double mh = M[j][0] * vox;
        double mw = M[j][1] * vox;
        double md = M[j][2] * vox;
        g_coef[r*4 + 0] = (float)(mh * A[r]);
        g_coef[r*4 + 1] = (float)(mw * A[r]);
        g_coef[r*4 + 2] = (float)(md * A[r]);
        g_coef[r*4 + 3] = (float)(A[r] * (b[j] - mh*ch - mw*cw - md*cd) + Cadd[r]);
    }
}

// smem layout: addr = c*SSTRIDE + 9*(td&15) + 16*(tw&1) + 4*(tw>>1) + 164*(td>>4)
//  - injective (proven: 9a+16b+4c unique for a<16,b<2,c<4; +164*e separates halves)
//  - gather-warp (a = l&15, b = (l>>4)&1 vary): banks 9a+16b mod 32 = full perm
//  - store-warp (dp = 4*wi + (l>>3), wp = l&7): banks 9j+16(wp&1)+4(wp>>1) = full perm
__device__ __forceinline__ int soff(int td, int tw) {
    return 9 * (td & 15) + 16 * (tw & 1) + 4 * (tw >> 1) + 164 * (td >> 4);
}

__global__ __launch_bounds__(256, 5)
void sample_kernel(const float* __restrict__ in, float* __restrict__ out) {
    __shared__ float sbuf[C_ * SSTRIDE];   // 41984 B

    const int tid  = threadIdx.x;
    const int lane = tid & 31;
    const int wi   = tid >> 5;

    // Gather mapping: warp = 16 d x 2 w. td bit4 from warp bit0, tw high bits from warp bits 1-2.
    const int td = (lane & 15) | ((wi & 1) << 4);
    const int tw = ((lane >> 4) & 1) | ((wi >> 1) << 1);

    const int d = blockIdx.z * 32 + td;
    const int h = blockIdx.y;
    const int w = blockIdx.x * 8 + tw;

    const float fh = (float)h, fw = (float)w, fd = (float)d;
    const float ix = fmaf(g_coef[0], fh, fmaf(g_coef[1], fw, fmaf(g_coef[2],  fd, g_coef[3])));
    const float iy = fmaf(g_coef[4], fh, fmaf(g_coef[5], fw, fmaf(g_coef[6],  fd, g_coef[7])));
    const float iz = fmaf(g_coef[8], fh, fmaf(g_coef[9], fw, fmaf(g_coef[10], fd, g_coef[11])));

    const float xf = floorf(ix); const int x0 = (int)xf; const float tx = ix - xf;
    const float yf = floorf(iy); const int y0 = (int)yf; const float ty = iy - yf;
    const float zf = floorf(iz); const int z0 = (int)zf; const float tz = iz - zf;

    const float wx0 = (x0 >= 0  && x0 <  W_)     ? (1.0f - tx) : 0.0f;
    const float wx1 = (x0 >= -1 && x0 <  W_ - 1) ? tx          : 0.0f;
    const float wy0 = (y0 >= 0  && y0 <  H_)     ? (1.0f - ty) : 0.0f;
    const float wy1 = (y0 >= -1 && y0 <  H_ - 1) ? ty          : 0.0f;
    const float wz0 = (z0 >= 0  && z0 <  D_)     ? (1.0f - tz) : 0.0f;
    const float wz1 = (z0 >= -1 && z0 <  D_ - 1) ? tz          : 0.0f;

    const int xc0 = min(max(x0,     0), W_ - 1);
    const int xc1 = min(max(x0 + 1, 0), W_ - 1);
    const int yo0 = min(max(y0,     0), H_ - 1) * W_;
    const int yo1 = min(max(y0 + 1, 0), H_ - 1) * W_;
    const int zo0 = min(max(z0,     0), D_ - 1) * HW_;
    const int zo1 = min(max(z0 + 1, 0), D_ - 1) * HW_;

    const int o000 = zo0 + yo0 + xc0;
    const int o001 = zo0 + yo0 + xc1;
    const int o010 = zo0 + yo1 + xc0;
    const int o011 = zo0 + yo1 + xc1;
    const int o100 = zo1 + yo0 + xc0;
    const int o101 = zo1 + yo0 + xc1;
    const int o110 = zo1 + yo1 + xc0;
    const int o111 = zo1 + yo1 + xc1;

    const float W000 = wz0 * wy0 * wx0;
    const float W001 = wz0 * wy0 * wx1;
    const float W010 = wz0 * wy1 * wx0;
    const float W011 = wz0 * wy1 * wx1;
    const float W100 = wz1 * wy0 * wx0;
    const float W101 = wz1 * wy0 * wx1;
    const float W110 = wz1 * wy1 * wx0;
    const float W111 = wz1 * wy1 * wx1;

    float* sp = sbuf + soff(td, tw);
    const float* __restrict__ base = in;

#pragma unroll 4
    for (int c = 0; c < C_; c++) {
        float acc;
        acc =       W000 * __ldg(base + o000);
        acc = fmaf(W001, __ldg(base + o001), acc);
        acc = fmaf(W010, __ldg(base + o010), acc);
        acc = fmaf(W011, __ldg(base + o011), acc);
        acc = fmaf(W100, __ldg(base + o100), acc);
        acc = fmaf(W101, __ldg(base + o101), acc);
        acc = fmaf(W110, __ldg(base + o110), acc);
        acc = fmaf(W111, __ldg(base + o111), acc);
        sp[c * SSTRIDE] = acc;
        base += DHW_;
    }

    __syncthreads();

    // Store phase: dp = 4*warp + (lane>>3), wp = lane&7  -> 4x32B segments per warp-store
    const int wp = lane & 7;
    const int dp = wi * 4 + (lane >> 3);
    const float* rp = sbuf + soff(dp, wp);
    float* __restrict__ po = out + (size_t)(blockIdx.z * 32 + dp) * HW_
                                 + (size_t)h * W_ + blockIdx.x * 8 + wp;

#pragma unroll
    for (int c = 0; c < C_; c++) {
        po[(size_t)c * DHW_] = rp[c * SSTRIDE];
    }
}

extern "C" void kernel_launch(void* const* d_in, const int* in_sizes, int n_in,
                              void* d_out, int out_size) {
    const float* past_grid  = (const float*)d_in[0];
    const float* voxelsize  = (const float*)d_in[1];
    const float* rot_past   = (const float*)d_in[2];
    const float* trans_past = (const float*)d_in[3];
    const float* rot_cur    = (const float*)d_in[4];
    const float* trans_cur  = (const float*)d_in[5];
    float* out = (float*)d_out;

    setup_kernel<<<1, 1>>>(voxelsize, rot_past, trans_past, rot_cur, trans_cur);

    dim3 grid(W_ / 8, H_, D_ / 32);   // 24 x 192 x 2 = 9216 blocks
    sample_kernel<<<grid, 256>>>(past_grid, out);
}